// round 2
// baseline (speedup 1.0000x reference)
#include <cuda_runtime.h>
#include <math.h>

#define BB 8
#define TT 2048
#define CC 1024
#define HH 64

// scratch for q,k,v projections (B*T*H floats each = 4 MB each)
__device__ float g_q[BB*TT*HH];
__device__ float g_k[BB*TT*HH];
__device__ float g_v[BB*TT*HH];

// ---------------------------------------------------------------------------
// Kernel 1: fused QKV projection.  out[b,t,h] = sum_c x[b,t,c] * W[c,h]
// Grid: (256, 3) ; block 256.  Each block: 64 rows x 64 cols output tile.
// ---------------------------------------------------------------------------
__global__ __launch_bounds__(256) void proj_kernel(
    const float* __restrict__ x,
    const float* __restrict__ Wq,
    const float* __restrict__ Wk,
    const float* __restrict__ Wv)
{
    __shared__ float sX[64][68];   // [c][m]  (x tile transposed)
    __shared__ float sW[64][68];   // [c][h]

    const int tid  = threadIdx.x;
    const int row0 = blockIdx.x * 64;
    const int ty   = tid >> 4;     // 0..15 -> 4 rows each
    const int tx   = tid & 15;     // 0..15 -> 4 cols each

    const float* W;
    float* out;
    if (blockIdx.y == 0)      { W = Wq; out = g_q; }
    else if (blockIdx.y == 1) { W = Wk; out = g_k; }
    else                      { W = Wv; out = g_v; }

    float acc[4][4];
    #pragma unroll
    for (int i = 0; i < 4; i++)
        #pragma unroll
        for (int j = 0; j < 4; j++) acc[i][j] = 0.f;

    for (int c0 = 0; c0 < CC; c0 += 64) {
        // load x tile 64(m) x 64(c), store transposed sX[c][m]
        #pragma unroll
        for (int i = 0; i < 4; i++) {
            int e  = tid + i * 256;
            int m  = e >> 4;
            int c4 = (e & 15) * 4;
            float4 v = *(const float4*)&x[(size_t)(row0 + m) * CC + c0 + c4];
            sX[c4 + 0][m] = v.x;
            sX[c4 + 1][m] = v.y;
            sX[c4 + 2][m] = v.z;
            sX[c4 + 3][m] = v.w;
        }
        // load W tile 64(c) x 64(h) natural layout
        #pragma unroll
        for (int i = 0; i < 4; i++) {
            int e  = tid + i * 256;
            int c  = e >> 4;
            int h4 = (e & 15) * 4;
            *(float4*)&sW[c][h4] = *(const float4*)&W[(size_t)(c0 + c) * HH + h4];
        }
        __syncthreads();

        #pragma unroll 8
        for (int c = 0; c < 64; c++) {
            float4 a  = *(float4*)&sX[c][ty * 4];
            float4 bv = *(float4*)&sW[c][tx * 4];
            float av[4] = {a.x, a.y, a.z, a.w};
            float bw[4] = {bv.x, bv.y, bv.z, bv.w};
            #pragma unroll
            for (int i = 0; i < 4; i++)
                #pragma unroll
                for (int j = 0; j < 4; j++)
                    acc[i][j] += av[i] * bw[j];
        }
        __syncthreads();
    }

    #pragma unroll
    for (int i = 0; i < 4; i++) {
        float4 o = make_float4(acc[i][0], acc[i][1], acc[i][2], acc[i][3]);
        *(float4*)&out[(size_t)(row0 + ty * 4 + i) * HH + tx * 4] = o;
    }
}

// ---------------------------------------------------------------------------
// Kernel 2: causal flash attention.
// Grid: (T/64, B); block 256.  BM=64 queries/block, BN=32 kv per tile.
// Thread (ty,tx): rows ty*4..+3, score cols tx*2..+1, O cols tx*4..+3.
// ---------------------------------------------------------------------------
__global__ __launch_bounds__(256) void attn_kernel(float* __restrict__ out)
{
    __shared__ float sQ[64][68];   // [h][m]  (pre-scaled by 1/sqrt(H))
    __shared__ float sK[64][40];   // [h][n]
    __shared__ float sV[32][68];   // [n][h]
    __shared__ float sP[32][68];   // [n][m]

    const int tid = threadIdx.x;
    const int b   = blockIdx.y;
    const int qt  = (int)(gridDim.x - 1) - (int)blockIdx.x;  // heavy tiles first
    const int q0  = qt * 64;
    const int ty  = tid >> 4;
    const int tx  = tid & 15;

    const float* q = g_q + (size_t)b * TT * HH;
    const float* k = g_k + (size_t)b * TT * HH;
    const float* v = g_v + (size_t)b * TT * HH;

    // load Q tile transposed, pre-scaled
    const float qscale = 0.125f;   // 1/sqrt(64)
    #pragma unroll
    for (int i = 0; i < 4; i++) {
        int e  = tid + i * 256;
        int m  = e >> 4;
        int h4 = (e & 15) * 4;
        float4 val = *(const float4*)&q[(size_t)(q0 + m) * HH + h4];
        sQ[h4 + 0][m] = val.x * qscale;
        sQ[h4 + 1][m] = val.y * qscale;
        sQ[h4 + 2][m] = val.z * qscale;
        sQ[h4 + 3][m] = val.w * qscale;
    }

    float m_i[4], l_i[4], acc[4][4];
    #pragma unroll
    for (int i = 0; i < 4; i++) {
        m_i[i] = -INFINITY;
        l_i[i] = 0.f;
        #pragma unroll
        for (int j = 0; j < 4; j++) acc[i][j] = 0.f;
    }

    const int n_tiles = qt * 2 + 2;       // kv covers [0, q0+64)
    for (int t = 0; t < n_tiles; t++) {
        const int kv0 = t * 32;
        // load K tile 32(n) x 64(h) transposed -> sK[h][n]
        #pragma unroll
        for (int i = 0; i < 2; i++) {
            int e  = tid + i * 256;
            int n  = e >> 4;
            int h4 = (e & 15) * 4;
            float4 val = *(const float4*)&k[(size_t)(kv0 + n) * HH + h4];
            sK[h4 + 0][n] = val.x;
            sK[h4 + 1][n] = val.y;
            sK[h4 + 2][n] = val.z;
            sK[h4 + 3][n] = val.w;
        }
        // load V tile 32(n) x 64(h) natural
        #pragma unroll
        for (int i = 0; i < 2; i++) {
            int e  = tid + i * 256;
            int n  = e >> 4;
            int h4 = (e & 15) * 4;
            *(float4*)&sV[n][h4] = *(const float4*)&v[(size_t)(kv0 + n) * HH + h4];
        }
        __syncthreads();   // K/V visible; previous-iter sP readers done

        // S = Q K^T for this tile: 4 rows x 2 cols per thread
        float s[4][2];
        #pragma unroll
        for (int i = 0; i < 4; i++) { s[i][0] = 0.f; s[i][1] = 0.f; }
        #pragma unroll 8
        for (int h = 0; h < 64; h++) {
            float4 a  = *(float4*)&sQ[h][ty * 4];
            float2 bb = *(float2*)&sK[h][tx * 2];
            s[0][0] += a.x * bb.x;  s[0][1] += a.x * bb.y;
            s[1][0] += a.y * bb.x;  s[1][1] += a.y * bb.y;
            s[2][0] += a.z * bb.x;  s[2][1] += a.z * bb.y;
            s[3][0] += a.w * bb.x;  s[3][1] += a.w * bb.y;
        }

        // causal mask (only tiles touching the diagonal band)
        if (kv0 + 32 > q0) {
            #pragma unroll
            for (int i = 0; i < 4; i++) {
                int qr = q0 + ty * 4 + i;
                #pragma unroll
                for (int j = 0; j < 2; j++) {
                    int kc = kv0 + tx * 2 + j;
                    if (kc > qr) s[i][j] = -INFINITY;
                }
            }
        }

        // online softmax per row (row owned by 16 lanes: shfl-xor width 16)
        #pragma unroll
        for (int i = 0; i < 4; i++) {
            float mx = fmaxf(s[i][0], s[i][1]);
            #pragma unroll
            for (int off = 8; off >= 1; off >>= 1)
                mx = fmaxf(mx, __shfl_xor_sync(0xffffffffu, mx, off));
            float m_new = fmaxf(m_i[i], mx);
            float alpha = __expf(m_i[i] - m_new);
            float p0 = __expf(s[i][0] - m_new);
            float p1 = __expf(s[i][1] - m_new);
            float rs = p0 + p1;
            #pragma unroll
            for (int off = 8; off >= 1; off >>= 1)
                rs += __shfl_xor_sync(0xffffffffu, rs, off);
            l_i[i] = l_i[i] * alpha + rs;
            m_i[i] = m_new;
            s[i][0] = p0;
            s[i][1] = p1;
            #pragma unroll
            for (int j = 0; j < 4; j++) acc[i][j] *= alpha;
        }

        // store P transposed -> sP[n][m]
        #pragma unroll
        for (int i = 0; i < 4; i++) {
            sP[tx * 2 + 0][ty * 4 + i] = s[i][0];
            sP[tx * 2 + 1][ty * 4 + i] = s[i][1];
        }
        __syncthreads();

        // O += P * V : per thread 4 rows x 4 h-cols, inner over 32 kv
        #pragma unroll 8
        for (int n = 0; n < 32; n++) {
            float4 a  = *(float4*)&sP[n][ty * 4];
            float4 bb = *(float4*)&sV[n][tx * 4];
            acc[0][0] += a.x * bb.x; acc[0][1] += a.x * bb.y; acc[0][2] += a.x * bb.z; acc[0][3] += a.x * bb.w;
            acc[1][0] += a.y * bb.x; acc[1][1] += a.y * bb.y; acc[1][2] += a.y * bb.z; acc[1][3] += a.y * bb.w;
            acc[2][0] += a.z * bb.x; acc[2][1] += a.z * bb.y; acc[2][2] += a.z * bb.z; acc[2][3] += a.z * bb.w;
            acc[3][0] += a.w * bb.x; acc[3][1] += a.w * bb.y; acc[3][2] += a.w * bb.z; acc[3][3] += a.w * bb.w;
        }
        __syncthreads();   // protect sK/sV reload next iteration
    }

    // epilogue: normalize and write
    #pragma unroll
    for (int i = 0; i < 4; i++) {
        float inv = 1.f / l_i[i];
        float4 o = make_float4(acc[i][0] * inv, acc[i][1] * inv,
                               acc[i][2] * inv, acc[i][3] * inv);
        *(float4*)&out[((size_t)b * TT + q0 + ty * 4 + i) * HH + tx * 4] = o;
    }
}

extern "C" void kernel_launch(void* const* d_in, const int* in_sizes, int n_in,
                              void* d_out, int out_size)
{
    const float* x  = (const float*)d_in[0];
    const float* Wq = (const float*)d_in[1];
    const float* Wk = (const float*)d_in[2];
    const float* Wv = (const float*)d_in[3];
    float* out = (float*)d_out;

    proj_kernel<<<dim3(BB * TT / 64, 3), 256>>>(x, Wq, Wk, Wv);
    attn_kernel<<<dim3(TT / 64, BB), 256>>>(out);
}

// round 3
// speedup vs baseline: 1.2714x; 1.2714x over previous
#include <cuda_runtime.h>
#include <math.h>

#define BB 8
#define TT 2048
#define CC 1024
#define HH 64

// scratch for q,k,v projections (B*T*H floats each = 4 MB each)
__device__ float g_q[BB*TT*HH];
__device__ float g_k[BB*TT*HH];
__device__ float g_v[BB*TT*HH];
__device__ int   g_ctr;

// ---------------------------------------------------------------------------
// Kernel 1: fused QKV projection.  out[b,t,h] = sum_c x[b,t,c] * W[c,h]
// Grid: (256, 3) ; block 256.  Each block: 64 rows x 64 cols output tile.
// ---------------------------------------------------------------------------
__global__ __launch_bounds__(256) void proj_kernel(
    const float* __restrict__ x,
    const float* __restrict__ Wq,
    const float* __restrict__ Wk,
    const float* __restrict__ Wv)
{
    __shared__ float sX[64][68];   // [c][m]  (x tile transposed)
    __shared__ float sW[64][68];   // [c][h]

    const int tid  = threadIdx.x;
    const int row0 = blockIdx.x * 64;
    const int ty   = tid >> 4;     // 0..15 -> 4 rows each
    const int tx   = tid & 15;     // 0..15 -> 4 cols each

    const float* W;
    float* out;
    if (blockIdx.y == 0)      { W = Wq; out = g_q; }
    else if (blockIdx.y == 1) { W = Wk; out = g_k; }
    else                      { W = Wv; out = g_v; }

    float acc[4][4];
    #pragma unroll
    for (int i = 0; i < 4; i++)
        #pragma unroll
        for (int j = 0; j < 4; j++) acc[i][j] = 0.f;

    for (int c0 = 0; c0 < CC; c0 += 64) {
        #pragma unroll
        for (int i = 0; i < 4; i++) {
            int e  = tid + i * 256;
            int m  = e >> 4;
            int c4 = (e & 15) * 4;
            float4 v = *(const float4*)&x[(size_t)(row0 + m) * CC + c0 + c4];
            sX[c4 + 0][m] = v.x;
            sX[c4 + 1][m] = v.y;
            sX[c4 + 2][m] = v.z;
            sX[c4 + 3][m] = v.w;
        }
        #pragma unroll
        for (int i = 0; i < 4; i++) {
            int e  = tid + i * 256;
            int c  = e >> 4;
            int h4 = (e & 15) * 4;
            *(float4*)&sW[c][h4] = *(const float4*)&W[(size_t)(c0 + c) * HH + h4];
        }
        __syncthreads();

        #pragma unroll 8
        for (int c = 0; c < 64; c++) {
            float4 a  = *(float4*)&sX[c][ty * 4];
            float4 bv = *(float4*)&sW[c][tx * 4];
            float av[4] = {a.x, a.y, a.z, a.w};
            float bw[4] = {bv.x, bv.y, bv.z, bv.w};
            #pragma unroll
            for (int i = 0; i < 4; i++)
                #pragma unroll
                for (int j = 0; j < 4; j++)
                    acc[i][j] += av[i] * bw[j];
        }
        __syncthreads();
    }

    #pragma unroll
    for (int i = 0; i < 4; i++) {
        float4 o = make_float4(acc[i][0], acc[i][1], acc[i][2], acc[i][3]);
        *(float4*)&out[(size_t)(row0 + ty * 4 + i) * HH + tx * 4] = o;
    }
}

__global__ void reset_ctr_kernel() { g_ctr = 0; }

// ---------------------------------------------------------------------------
// Kernel 2: persistent causal flash attention with work stealing.
// Grid: 296 CTAs (2/SM), block 256.  Job = (batch, 32-row q-tile); 512 jobs,
// pulled heavy-first from g_ctr.  BN=64 kv per chunk.
// Dynamic smem layout (floats):
//   sQ [64][36]  @0       (Q tile transposed [h][m], pre-scaled)
//   sK [64][68]  @2304    ([h][n])
//   sV [64][68]  @6656    ([n][h])
//   sP [64][36]  @11008   ([n][m])
// total 13312 floats = 53248 B
// ---------------------------------------------------------------------------
#define ATTN_CTAS 296
#define SMEM_FLOATS 13312

__global__ __launch_bounds__(256) void attn_kernel(float* __restrict__ out)
{
    extern __shared__ float sm[];
    float* sQ = sm;             // stride 36
    float* sK = sm + 2304;      // stride 68
    float* sV = sm + 6656;      // stride 68
    float* sP = sm + 11008;     // stride 36

    __shared__ int sJob;

    const int tid = threadIdx.x;
    const int ty  = tid >> 4;      // 0..15 -> 2 rows each
    const int tx  = tid & 15;      // 0..15 -> 4 cols each
    const int r   = ty * 2;

    for (;;) {
        if (tid == 0) sJob = atomicAdd(&g_ctr, 1);
        __syncthreads();           // also: previous job's smem reads are done
        const int job = sJob;
        if (job >= 512) break;

        const int qt = 63 - (job >> 3);    // heavy jobs first
        const int b  = job & 7;
        const int q0 = qt * 32;

        const float* q = g_q + (size_t)b * TT * HH;
        const float* k = g_k + (size_t)b * TT * HH;
        const float* v = g_v + (size_t)b * TT * HH;

        // load Q tile 32(m) x 64(h), transposed & pre-scaled by 1/sqrt(H)
        #pragma unroll
        for (int i = 0; i < 2; i++) {
            int e  = tid + i * 256;
            int m  = e >> 4;
            int h4 = (e & 15) * 4;
            float4 val = *(const float4*)&q[(size_t)(q0 + m) * HH + h4];
            sQ[(h4 + 0) * 36 + m] = val.x * 0.125f;
            sQ[(h4 + 1) * 36 + m] = val.y * 0.125f;
            sQ[(h4 + 2) * 36 + m] = val.z * 0.125f;
            sQ[(h4 + 3) * 36 + m] = val.w * 0.125f;
        }

        float m_i[2] = {-INFINITY, -INFINITY};
        float l_i[2] = {0.f, 0.f};
        float acc[2][4];
        #pragma unroll
        for (int i = 0; i < 2; i++)
            #pragma unroll
            for (int j = 0; j < 4; j++) acc[i][j] = 0.f;

        const int n_chunks = (qt + 2) >> 1;   // ceil((qt+1)/2)
        for (int t = 0; t < n_chunks; t++) {
            const int kv0 = t * 64;
            __syncthreads();   // previous chunk's sK/sV/sP readers done

            // load K tile 64(n) x 64(h) transposed -> sK[h][n]
            #pragma unroll
            for (int i = 0; i < 4; i++) {
                int e  = tid + i * 256;
                int n  = e >> 4;
                int h4 = (e & 15) * 4;
                float4 val = *(const float4*)&k[(size_t)(kv0 + n) * HH + h4];
                sK[(h4 + 0) * 68 + n] = val.x;
                sK[(h4 + 1) * 68 + n] = val.y;
                sK[(h4 + 2) * 68 + n] = val.z;
                sK[(h4 + 3) * 68 + n] = val.w;
            }
            // load V tile 64(n) x 64(h) natural -> sV[n][h]
            #pragma unroll
            for (int i = 0; i < 4; i++) {
                int e  = tid + i * 256;
                int n  = e >> 4;
                int h4 = (e & 15) * 4;
                *(float4*)&sV[n * 68 + h4] =
                    *(const float4*)&v[(size_t)(kv0 + n) * HH + h4];
            }
            __syncthreads();   // K/V (and Q on first chunk) visible

            // S = Q K^T : 2 rows x 4 cols per thread
            float s[2][4];
            #pragma unroll
            for (int j = 0; j < 4; j++) { s[0][j] = 0.f; s[1][j] = 0.f; }
            #pragma unroll 8
            for (int h = 0; h < 64; h++) {
                float2 a  = *(float2*)&sQ[h * 36 + r];
                float4 bb = *(float4*)&sK[h * 68 + tx * 4];
                s[0][0] += a.x * bb.x;  s[0][1] += a.x * bb.y;
                s[0][2] += a.x * bb.z;  s[0][3] += a.x * bb.w;
                s[1][0] += a.y * bb.x;  s[1][1] += a.y * bb.y;
                s[1][2] += a.y * bb.z;  s[1][3] += a.y * bb.w;
            }

            // causal mask (chunks touching the diagonal band)
            if (kv0 + 64 > q0) {
                #pragma unroll
                for (int i = 0; i < 2; i++) {
                    int qr = q0 + r + i;
                    #pragma unroll
                    for (int j = 0; j < 4; j++) {
                        if (kv0 + tx * 4 + j > qr) s[i][j] = -INFINITY;
                    }
                }
            }

            // online softmax; row owned by 16 lanes (shfl width 16)
            #pragma unroll
            for (int i = 0; i < 2; i++) {
                float mx = fmaxf(fmaxf(s[i][0], s[i][1]), fmaxf(s[i][2], s[i][3]));
                #pragma unroll
                for (int off = 8; off >= 1; off >>= 1)
                    mx = fmaxf(mx, __shfl_xor_sync(0xffffffffu, mx, off));
                float m_new = fmaxf(m_i[i], mx);
                float alpha = __expf(m_i[i] - m_new);
                float p0 = __expf(s[i][0] - m_new);
                float p1 = __expf(s[i][1] - m_new);
                float p2 = __expf(s[i][2] - m_new);
                float p3 = __expf(s[i][3] - m_new);
                float rs = (p0 + p1) + (p2 + p3);
                #pragma unroll
                for (int off = 8; off >= 1; off >>= 1)
                    rs += __shfl_xor_sync(0xffffffffu, rs, off);
                l_i[i] = l_i[i] * alpha + rs;
                m_i[i] = m_new;
                s[i][0] = p0; s[i][1] = p1; s[i][2] = p2; s[i][3] = p3;
                #pragma unroll
                for (int j = 0; j < 4; j++) acc[i][j] *= alpha;
            }

            // store P transposed -> sP[n][m]
            #pragma unroll
            for (int j = 0; j < 4; j++) {
                sP[(tx * 4 + j) * 36 + r + 0] = s[0][j];
                sP[(tx * 4 + j) * 36 + r + 1] = s[1][j];
            }
            __syncthreads();   // sP complete

            // O += P * V : 2 rows x 4 h-cols per thread, inner over 64 kv
            #pragma unroll 8
            for (int n = 0; n < 64; n++) {
                float2 a  = *(float2*)&sP[n * 36 + r];
                float4 bb = *(float4*)&sV[n * 68 + tx * 4];
                acc[0][0] += a.x * bb.x; acc[0][1] += a.x * bb.y;
                acc[0][2] += a.x * bb.z; acc[0][3] += a.x * bb.w;
                acc[1][0] += a.y * bb.x; acc[1][1] += a.y * bb.y;
                acc[1][2] += a.y * bb.z; acc[1][3] += a.y * bb.w;
            }
        }

        // epilogue: normalize and write
        #pragma unroll
        for (int i = 0; i < 2; i++) {
            float inv = 1.f / l_i[i];
            float4 o = make_float4(acc[i][0] * inv, acc[i][1] * inv,
                                   acc[i][2] * inv, acc[i][3] * inv);
            *(float4*)&out[((size_t)b * TT + q0 + r + i) * HH + tx * 4] = o;
        }
    }
}

extern "C" void kernel_launch(void* const* d_in, const int* in_sizes, int n_in,
                              void* d_out, int out_size)
{
    const float* x  = (const float*)d_in[0];
    const float* Wq = (const float*)d_in[1];
    const float* Wk = (const float*)d_in[2];
    const float* Wv = (const float*)d_in[3];
    float* out = (float*)d_out;

    cudaFuncSetAttribute(attn_kernel,
                         cudaFuncAttributeMaxDynamicSharedMemorySize,
                         SMEM_FLOATS * (int)sizeof(float));

    reset_ctr_kernel<<<1, 1>>>();
    proj_kernel<<<dim3(BB * TT / 64, 3), 256>>>(x, Wq, Wk, Wv);
    attn_kernel<<<ATTN_CTAS, 256, SMEM_FLOATS * sizeof(float)>>>(out);
}